// round 17
// baseline (speedup 1.0000x reference)
#include <cuda_runtime.h>
#include <cuda_bf16.h>

// Problem constants (fixed by the dataset)
#define D_CH   256
#define GRID_H 384
#define GRID_W 384
#define TOK_PER_BLK 16

// Token-index map: g_map[r*W+c] = token id. Zero-initialized at module load.
// Validity is established by a coords round-trip at probe time, so no init /
// clear kernel is needed (never-occupied cells stay 0; a stale 0 only
// validates if token 0 truly occupies that cell).
__device__ int g_map[GRID_H * GRID_W];

// ---------------------------------------------------------------------------
// Kernel 1: scatter token ids into the map
// ---------------------------------------------------------------------------
__global__ void scatter_kernel(const int* __restrict__ coords, int n) {
    int i = blockIdx.x * blockDim.x + threadIdx.x;
    if (i < n) {
        g_map[coords[2 * i] * GRID_W + coords[2 * i + 1]] = i;
    }
}

// ---------------------------------------------------------------------------
// Kernel 2: gather-conv, (D, N) channel-major output.
//   256 threads = 8 warps; 16 tokens/block.
//   Warp w: tokens (w&3)*4 .. +3, channel half (w>>2): float4 index
//   coff+lane with coff = (w>>2)*32. Tap-major loop: weight float4 loaded
//   ONCE per tap (amortized over 4 tokens); dead taps skipped by
//   warp-uniform branches (nbr value is lane-invariant -> no divergence,
//   no wasted gather traffic).
// ---------------------------------------------------------------------------
__global__ __launch_bounds__(256, 5) void conv_kernel(
    const float* __restrict__ tokens,   // [N, 256]
    const int*   __restrict__ coords,   // [N, 2]
    const float* __restrict__ weight,   // [256][9]
    const float* __restrict__ bias,     // [256]
    float*       __restrict__ out,      // [256, N]  (channel-major)
    int n)
{
    __shared__ float  wT[9][D_CH];            // wT[tap][channel]     (9 KB)
    __shared__ float4 sOut4[TOK_PER_BLK][65]; // [token][c4] (+pad)   (16.6 KB)
    __shared__ int    nbr[TOK_PER_BLK][9];    // neighbor idx or -1

    const int tid     = threadIdx.x;
    const int lane    = tid & 31;
    const int warp    = tid >> 5;             // 0..7
    const int tokbase = blockIdx.x * TOK_PER_BLK;

    // --- transposed weights: wT[k][d] = weight[d*9 + k] ---
    #pragma unroll
    for (int i = tid; i < 9 * D_CH; i += 256) {
        int d = i & 255;
        int k = i >> 8;
        wT[k][d] = weight[d * 9 + k];
    }

    // --- neighbor probes: 16 tokens x 9 taps, coords round-trip validation ---
    if (tid < TOK_PER_BLK * 9) {
        int t   = tid / 9;
        int k   = tid % 9;
        int tok = tokbase + t;
        int idx = -1;
        if (tok < n) {
            int r  = coords[2 * tok];
            int c  = coords[2 * tok + 1];
            int rr = r + (k / 3) - 1;
            int cc = c + (k % 3) - 1;
            if (rr >= 0 && rr < GRID_H && cc >= 0 && cc < GRID_W) {
                int j = g_map[rr * GRID_W + cc];
                if (coords[2 * j] == rr && coords[2 * j + 1] == cc) idx = j;
            }
        }
        nbr[t][k] = idx;
    }
    __syncthreads();

    // --- Phase A: tap-major gather. 4 tokens/warp, half-row channels. ---
    const float4* tok4  = reinterpret_cast<const float4*>(tokens);
    const float4* bias4 = reinterpret_cast<const float4*>(bias);

    const int tg   = (warp & 3) * 4;          // first of this warp's 4 tokens
    const int coff = (warp >> 2) * 32;        // float4 channel offset (0 | 32)
    const int ci   = coff + lane;             // this lane's float4 index

    const float4 bv = bias4[ci];
    float4 acc0 = bv, acc1 = bv, acc2 = bv, acc3 = bv;

    #pragma unroll
    for (int k = 0; k < 9; k++) {
        const float4 wv = reinterpret_cast<const float4*>(&wT[k][0])[lane + coff];

        int j0 = nbr[tg + 0][k];
        int j1 = nbr[tg + 1][k];
        int j2 = nbr[tg + 2][k];
        int j3 = nbr[tg + 3][k];

        if (j0 >= 0) {                        // warp-uniform branch
            float4 v = tok4[(size_t)j0 * (D_CH / 4) + ci];
            acc0.x = fmaf(wv.x, v.x, acc0.x); acc0.y = fmaf(wv.y, v.y, acc0.y);
            acc0.z = fmaf(wv.z, v.z, acc0.z); acc0.w = fmaf(wv.w, v.w, acc0.w);
        }
        if (j1 >= 0) {
            float4 v = tok4[(size_t)j1 * (D_CH / 4) + ci];
            acc1.x = fmaf(wv.x, v.x, acc1.x); acc1.y = fmaf(wv.y, v.y, acc1.y);
            acc1.z = fmaf(wv.z, v.z, acc1.z); acc1.w = fmaf(wv.w, v.w, acc1.w);
        }
        if (j2 >= 0) {
            float4 v = tok4[(size_t)j2 * (D_CH / 4) + ci];
            acc2.x = fmaf(wv.x, v.x, acc2.x); acc2.y = fmaf(wv.y, v.y, acc2.y);
            acc2.z = fmaf(wv.z, v.z, acc2.z); acc2.w = fmaf(wv.w, v.w, acc2.w);
        }
        if (j3 >= 0) {
            float4 v = tok4[(size_t)j3 * (D_CH / 4) + ci];
            acc3.x = fmaf(wv.x, v.x, acc3.x); acc3.y = fmaf(wv.y, v.y, acc3.y);
            acc3.z = fmaf(wv.z, v.z, acc3.z); acc3.w = fmaf(wv.w, v.w, acc3.w);
        }
    }

    // --- transpose staging: consecutive lanes -> conflict-free STS.128 ---
    sOut4[tg + 0][ci] = acc0;
    sOut4[tg + 1][ci] = acc1;
    sOut4[tg + 2][ci] = acc2;
    sOut4[tg + 3][ci] = acc3;
    __syncthreads();

    // --- Phase B: lane = channel; float4 over 4 consecutive tokens ---
    const float* sflat = reinterpret_cast<const float*>(&sOut4[0][0]);
    const int c = warp * 32 + lane;           // 0..255
    #pragma unroll
    for (int g = 0; g < 4; g++) {
        // bank of sflat[t*260 + c] == (4t + c) mod 32: distinct per lane
        float4 o;
        o.x = sflat[(4 * g + 0) * 260 + c];
        o.y = sflat[(4 * g + 1) * 260 + c];
        o.z = sflat[(4 * g + 2) * 260 + c];
        o.w = sflat[(4 * g + 3) * 260 + c];
        int tok = tokbase + 4 * g;
        if (tok + 3 < n) {
            *reinterpret_cast<float4*>(out + (size_t)c * n + tok) = o;
        } else {
            if (tok + 0 < n) out[(size_t)c * n + tok + 0] = o.x;
            if (tok + 1 < n) out[(size_t)c * n + tok + 1] = o.y;
            if (tok + 2 < n) out[(size_t)c * n + tok + 2] = o.z;
            if (tok + 3 < n) out[(size_t)c * n + tok + 3] = o.w;
        }
    }
}

// ---------------------------------------------------------------------------
// Launch — inputs bound BY ELEMENT COUNT (robust to metadata.txt ordering):
//   tokens : N*256 = 16,777,216 fp32    coords : 2N = 131,072 int32
//   weight : 2,304 fp32                 bias   : 256 fp32
// Output: fp32 (D, N) flattened (NumPy mixed advanced-indexing semantics).
// ---------------------------------------------------------------------------
extern "C" void kernel_launch(void* const* d_in, const int* in_sizes, int n_in,
                              void* d_out, int out_size) {
    int tok_i = 0;
    for (int i = 1; i < n_in; i++)
        if (in_sizes[i] > in_sizes[tok_i]) tok_i = i;
    const float* tokens = (const float*)d_in[tok_i];
    const int n = in_sizes[tok_i] / D_CH;   // 65536

    const int*   coords = nullptr;
    const float* weight = nullptr;
    const float* bias   = nullptr;
    for (int i = 0; i < n_in; i++) {
        if (i == tok_i) continue;
        const int sz = in_sizes[i];
        if (sz == 2 * n)         coords = (const int*)d_in[i];
        else if (sz == 9 * D_CH) weight = (const float*)d_in[i];
        else if (sz == D_CH)     bias   = (const float*)d_in[i];
    }
    if (!coords || !weight || !bias) {   // defensive positional fallback
        tokens = (const float*)d_in[0];
        coords = (const int*)d_in[1];
        weight = (const float*)d_in[2];
        bias   = (const float*)d_in[3];
    }

    float* out = (float*)d_out;

    // 1. scatter (validity via coords round-trip; no map init needed)
    scatter_kernel<<<(n + 255) / 256, 256>>>(coords, n);
    // 2. conv-gather with transposed output
    int nblocks = (n + TOK_PER_BLK - 1) / TOK_PER_BLK;
    conv_kernel<<<nblocks, 256>>>(tokens, coords, weight, bias, out, n);
}